// round 16
// baseline (speedup 1.0000x reference)
#include <cuda_runtime.h>

#define Bsz 64
#define Tn  16384
#define H1n 64
#define H2n 8

typedef unsigned long long u64;

// h2 history for the decoupled projection kernel: [b][t][cell], 32 MB.
__device__ float g_h2[(size_t)Bsz * Tn * H2n];

__device__ __forceinline__ u64 pk2(float lo, float hi) {
    u64 r; asm("mov.b64 %0, {%1,%2};" : "=l"(r) : "f"(lo), "f"(hi)); return r;
}
__device__ __forceinline__ float2 upk2(u64 v) {
    float2 f; asm("mov.b64 {%0,%1}, %2;" : "=f"(f.x), "=f"(f.y) : "l"(v)); return f;
}
__device__ __forceinline__ void fma2(u64 &d, u64 a, u64 b) {
    asm("fma.rn.f32x2 %0, %1, %2, %0;" : "+l"(d) : "l"(a), "l"(b));
}
__device__ __forceinline__ void add2(u64 &d, u64 a) {
    asm("add.rn.f32x2 %0, %0, %1;" : "+l"(d) : "l"(a));
}
__device__ __forceinline__ float tanh_(float v) {
    float r; asm("tanh.approx.f32 %0, %1;" : "=f"(r) : "f"(v)); return r;
}
__device__ __forceinline__ float sigm(float v) {
    return fmaf(0.5f, tanh_(0.5f * v), 0.5f);
}

// Main recurrence kernel (R12 topology minus the projection).
// One block per batch row, 11 warps (352 thr):
//   warps 0-7 : layer-1, lane = cellLocal*4 + gate, 8 cells/warp, 64-dot.
//   warp 8    : layer-2 update (lags 2), one lane per cell (lanes 0-7);
//               pbuf partials via 2x float4 LDS; h2(t-1) from a 2-deep
//               smem double buffer. h2 streamed to g_h2 (coalesced 32B STG,
//               off-chain). NO projection work in the loop at all.
//   warps 9-10: layer-2 input dot Wih2@h1[t-1], K-split 32/32, one step
//               ahead of warp 8, partials into double-buffered pbuf.
// h1 in a depth-4 smem ring; one __syncthreads per step orders hand-offs.
__global__ void __launch_bounds__(352, 1) lstm2_kernel(
    const float* __restrict__ x,
    const float* __restrict__ Wih1,
    const float* __restrict__ Whh1,
    const float* __restrict__ b1,
    const float* __restrict__ Wih2,
    const float* __restrict__ Whh2,
    const float* __restrict__ b2,
    float* __restrict__ out)
{
    const int b    = blockIdx.x;
    const int tid  = threadIdx.x;
    const int wid  = tid >> 5;
    const int lane = tid & 31;

    __shared__ __align__(16) float h1ring[4][H1n];
    __shared__ __align__(16) float pbuf[2][2][32];   // [phase][src][cell*4+gate]
    __shared__ __align__(16) float h2s[2][H2n];      // h2 double buffer

    const float* xb = x + (size_t)b * Tn;
    float*       h2g = g_h2 + (size_t)b * Tn * H2n;

    u64   w[32];                       // L1: 32; warp8: 16; helpers: 16
    float wih = 0.f, bias = 0.f;
    float c1 = 0.f, h1v = 0.f;
    float bias2 = 0.f;
    float c2 = 0.f, h2v = 0.f;
    int   cell = 0, q = 0;

    if (wid < 8) {
        cell = wid * 8 + (lane >> 2);
        q    = lane & 3;
        const int row = q * H1n + cell;
        const float2* wp = (const float2*)(Whh1 + row * H1n);
        #pragma unroll
        for (int k = 0; k < 32; k++) { float2 f = wp[k]; w[k] = pk2(f.x, f.y); }
        wih  = Wih1[row];
        bias = b1[row];
        if (tid < H1n) h1ring[3][tid] = 0.0f;   // h1[-1] = 0
    } else if (wid == 8) {
        // lanes 0-7: lane = cell, all 4 gates in-lane
        if (lane < H2n) {
            #pragma unroll
            for (int g = 0; g < 4; g++) {
                const int row = g * H2n + lane;
                const float2* wp = (const float2*)(Whh2 + row * H2n);
                #pragma unroll
                for (int j = 0; j < 4; j++) { float2 f = wp[j]; w[4 * g + j] = pk2(f.x, f.y); }
            }
            h2s[0][lane] = 0.0f;
            h2s[1][lane] = 0.0f;    // h2[-1] = 0 (read at t=2)
        }
    } else { // wid 9,10 : K-split input-dot helpers (32/32)
        cell = lane >> 2;
        q    = lane & 3;
        const int row = q * H2n + cell;
        const int koff = (wid == 9) ? 0 : 32;
        const float2* wp = (const float2*)(Wih2 + row * H1n + koff);
        #pragma unroll
        for (int k = 0; k < 16; k++) { float2 f = wp[k]; w[k] = pk2(f.x, f.y); }
        bias2 = (wid == 9) ? b2[row] : 0.f;
    }
    __syncthreads();

    float x_cur = xb[0];
    float x_n1  = xb[1];

    #pragma unroll 4
    for (int t = 0; t <= Tn + 1; ++t) {
        if (wid < 8) {
            if (t < Tn) {
                float x_n2 = (t + 2 < Tn) ? xb[t + 2] : 0.0f;
                u64 a0 = pk2(fmaf(x_cur, wih, bias), 0.0f);
                u64 a1 = pk2(0.f, 0.f), a2 = a1, a3 = a1;
                const ulonglong2* hp = (const ulonglong2*)(&h1ring[(t + 3) & 3][0]);
                #pragma unroll
                for (int k = 0; k < 8; k++) {
                    ulonglong2 ha = hp[2 * k];
                    ulonglong2 hb = hp[2 * k + 1];
                    fma2(a0, w[4 * k + 0], ha.x);
                    fma2(a1, w[4 * k + 1], ha.y);
                    fma2(a2, w[4 * k + 2], hb.x);
                    fma2(a3, w[4 * k + 3], hb.y);
                }
                add2(a0, a1); add2(a2, a3); add2(a0, a2);
                float2 s2 = upk2(a0);
                float g = s2.x + s2.y;
                float act = (q == 2) ? tanh_(g) : sigm(g);
                const unsigned bl = lane & ~3u;
                float ai = __shfl_sync(0xffffffffu, act, bl + 0);
                float af = __shfl_sync(0xffffffffu, act, bl + 1);
                float ag = __shfl_sync(0xffffffffu, act, bl + 2);
                float ao = __shfl_sync(0xffffffffu, act, bl + 3);
                c1  = fmaf(af, c1, ai * ag);
                h1v = ao * tanh_(c1);
                if (q == 0) h1ring[t & 3][cell] = h1v;
                x_cur = x_n1;
                x_n1  = x_n2;
            }
        } else if (wid == 8) {
            if (t >= 2 && lane < H2n) {
                const int s  = t - 2;
                const int ph = (t - 1) & 1;
                const float4 p0 = *(const float4*)&pbuf[ph][0][lane * 4];
                const float4 p1 = *(const float4*)&pbuf[ph][1][lane * 4];
                float gi = p0.x + p1.x;
                float gf = p0.y + p1.y;
                float gg = p0.z + p1.z;
                float go = p0.w + p1.w;
                // h2(t-3) written at iter t-1 into slot (t-1)&1
                const u64* hq = (const u64*)&h2s[ph][0];
                u64 h01 = hq[0], h23 = hq[1], h45 = hq[2], h67 = hq[3];
                u64 A = pk2(gi, 0.f), B = pk2(gf, 0.f);
                u64 C = pk2(gg, 0.f), D = pk2(go, 0.f);
                fma2(A, w[0],  h01); fma2(B, w[4],  h01);
                fma2(C, w[8],  h01); fma2(D, w[12], h01);
                fma2(A, w[1],  h23); fma2(B, w[5],  h23);
                fma2(C, w[9],  h23); fma2(D, w[13], h23);
                fma2(A, w[2],  h45); fma2(B, w[6],  h45);
                fma2(C, w[10], h45); fma2(D, w[14], h45);
                fma2(A, w[3],  h67); fma2(B, w[7],  h67);
                fma2(C, w[11], h67); fma2(D, w[15], h67);
                float2 fa = upk2(A), fb = upk2(B), fc = upk2(C), fd = upk2(D);
                float ti = sigm(fa.x + fa.y);
                float tf = sigm(fb.x + fb.y);
                float tg = tanh_(fc.x + fc.y);
                float to = sigm(fd.x + fd.y);
                c2  = fmaf(tf, c2, ti * tg);
                h2v = to * tanh_(c2);
                h2s[t & 1][lane] = h2v;
                h2g[(size_t)s * H2n + lane] = h2v;   // off-chain stream-out
            }
        } else { // wid 9,10 : layer-2 input-dot partials (for step s = t-1)
            if (t >= 1 && t <= Tn) {
                const int s = t - 1;
                u64 a0 = pk2(bias2, 0.0f), a1 = pk2(0.f, 0.f);
                const int koff = (wid == 9) ? 0 : 32;
                const ulonglong2* hp = (const ulonglong2*)(&h1ring[s & 3][koff]);
                #pragma unroll
                for (int k = 0; k < 4; k++) {
                    ulonglong2 ha = hp[2 * k];
                    ulonglong2 hb = hp[2 * k + 1];
                    fma2(a0, w[4 * k + 0], ha.x);
                    fma2(a1, w[4 * k + 1], ha.y);
                    fma2(a0, w[4 * k + 2], hb.x);
                    fma2(a1, w[4 * k + 3], hb.y);
                }
                add2(a0, a1);
                float2 s2 = upk2(a0);
                pbuf[t & 1][wid - 9][lane] = s2.x + s2.y;
            }
        }
        __syncthreads();
    }

    // final states: layout  y | h1 | c1 | h2 | c2  (each with leading dim 1)
    const int OH1 = Bsz * Tn;
    const int OC1 = OH1 + Bsz * H1n;
    const int OH2 = OC1 + Bsz * H1n;
    const int OC2 = OH2 + Bsz * H2n;
    if (wid < 8) {
        if (q == 0) {
            out[OH1 + b * H1n + cell] = h1v;
            out[OC1 + b * H1n + cell] = c1;
        }
    } else if (wid == 8) {
        if (lane < H2n) {
            out[OH2 + b * H2n + lane] = h2v;
            out[OC2 + b * H2n + lane] = c2;
        }
    }
}

// Decoupled projection: y[b][t] = Wout . h2[b][t] + bout + x[b][t].
// Trivially parallel over all 1M (b,t); ~40 MB traffic, full-chip.
__global__ void __launch_bounds__(256) proj_kernel(
    const float* __restrict__ x,
    const float* __restrict__ Wout,
    const float* __restrict__ bout,
    float* __restrict__ out)
{
    const int idx = blockIdx.x * 256 + threadIdx.x;   // b*Tn + t
    if (idx >= Bsz * Tn) return;
    const float4* h = (const float4*)(g_h2 + (size_t)idx * H2n);
    float4 h0 = h[0];
    float4 h1 = h[1];
    float acc0 = fmaf(h0.x, __ldg(Wout + 0), __ldg(bout));
    float acc1 = h0.y * __ldg(Wout + 1);
    acc0 = fmaf(h0.z, __ldg(Wout + 2), acc0);
    acc1 = fmaf(h0.w, __ldg(Wout + 3), acc1);
    acc0 = fmaf(h1.x, __ldg(Wout + 4), acc0);
    acc1 = fmaf(h1.y, __ldg(Wout + 5), acc1);
    acc0 = fmaf(h1.z, __ldg(Wout + 6), acc0);
    acc1 = fmaf(h1.w, __ldg(Wout + 7), acc1);
    out[idx] = acc0 + acc1 + x[idx];
}

extern "C" void kernel_launch(void* const* d_in, const int* in_sizes, int n_in,
                              void* d_out, int out_size) {
    const float* x     = (const float*)d_in[0];
    const float* Wih1  = (const float*)d_in[1];
    const float* Whh1  = (const float*)d_in[2];
    const float* b1    = (const float*)d_in[3];
    const float* Wih2  = (const float*)d_in[4];
    const float* Whh2  = (const float*)d_in[5];
    const float* b2    = (const float*)d_in[6];
    const float* Wout  = (const float*)d_in[7];
    const float* bout  = (const float*)d_in[8];
    float* out = (float*)d_out;

    lstm2_kernel<<<Bsz, 352>>>(x, Wih1, Whh1, b1, Wih2, Whh2, b2, out);
    proj_kernel<<<(Bsz * Tn + 255) / 256, 256>>>(x, Wout, bout, out);
}

// round 17
// speedup vs baseline: 1.0622x; 1.0622x over previous
#include <cuda_runtime.h>

#define Bsz 64
#define Tn  16384
#define H1n 64
#define H2n 8
#define RING 64
#define RSTR 8   // 32B rows: 16B-aligned for update-warp LDS.128 re-reads

typedef unsigned long long u64;

__device__ __forceinline__ u64 pk2(float lo, float hi) {
    u64 r; asm("mov.b64 %0, {%1,%2};" : "=l"(r) : "f"(lo), "f"(hi)); return r;
}
__device__ __forceinline__ float2 upk2(u64 v) {
    float2 f; asm("mov.b64 {%0,%1}, %2;" : "=f"(f.x), "=f"(f.y) : "l"(v)); return f;
}
__device__ __forceinline__ void fma2(u64 &d, u64 a, u64 b) {
    asm("fma.rn.f32x2 %0, %1, %2, %0;" : "+l"(d) : "l"(a), "l"(b));
}
__device__ __forceinline__ void add2(u64 &d, u64 a) {
    asm("add.rn.f32x2 %0, %0, %1;" : "+l"(d) : "l"(a));
}
__device__ __forceinline__ float tanh_(float v) {
    float r; asm("tanh.approx.f32 %0, %1;" : "=f"(r) : "f"(v)); return r;
}
__device__ __forceinline__ float sigm(float v) {
    return fmaf(0.5f, tanh_(0.5f * v), 0.5f);
}

// R12 topology, roles PERMUTED so layer-1 warps sit at HIGH wids (B300
// SMSP arbiter is highest-wid-first; the L1 chain gates the barrier, so it
// gets priority). One block per batch row, 11 warps (352 thr):
//   wid 0     : layer-2 update (lags 2), one lane per cell (lanes 0-7);
//               pbuf partials via 2x float4 LDS; h2(t-1) from the h2 ring.
//               Batched y projection every 32 steps.
//   wid 1,2   : layer-2 input dot Wih2@h1[t-1], K-split 32/32, one step
//               ahead of the update warp, into double-buffered pbuf.
//   wid 3-10  : layer-1, lane = cellLocal*4 + gate, 8 cells/warp, 64-dot.
//               Single-MUFU activation (select the arg, not the result).
// h1 in a depth-4 smem ring; one __syncthreads per step orders hand-offs.
__global__ void __launch_bounds__(352, 1) lstm2_kernel(
    const float* __restrict__ x,
    const float* __restrict__ Wih1,
    const float* __restrict__ Whh1,
    const float* __restrict__ b1,
    const float* __restrict__ Wih2,
    const float* __restrict__ Whh2,
    const float* __restrict__ b2,
    const float* __restrict__ Wout,
    const float* __restrict__ bout,
    float* __restrict__ out)
{
    const int b    = blockIdx.x;
    const int tid  = threadIdx.x;
    const int wid  = tid >> 5;
    const int lane = tid & 31;

    __shared__ __align__(16) float h1ring[4][H1n];
    __shared__ __align__(16) float pbuf[2][2][32];   // [phase][src][cell*4+gate]
    __shared__ __align__(16) float h2ring[RING * RSTR];

    const float* xb = x + (size_t)b * Tn;
    float*       yb = out + (size_t)b * Tn;

    u64   w[32];                       // L1: 32; update: 16; helpers: 16
    float wih = 0.f, bias = 0.f;
    float c1 = 0.f, h1v = 0.f;
    float w2h[8];                      // update warp: Wout taps
    float bias2 = 0.f, boutv = 0.f;
    float c2 = 0.f, h2v = 0.f;
    int   cell = 0, q = 0;

    if (wid >= 3) {                    // layer-1 warps (lw = wid-3)
        cell = (wid - 3) * 8 + (lane >> 2);
        q    = lane & 3;
        const int row = q * H1n + cell;
        const float2* wp = (const float2*)(Whh1 + row * H1n);
        #pragma unroll
        for (int k = 0; k < 32; k++) { float2 f = wp[k]; w[k] = pk2(f.x, f.y); }
        wih  = Wih1[row];
        bias = b1[row];
    } else if (wid == 0) {
        // lanes 0-7: lane = cell, all 4 gates in-lane
        if (lane < H2n) {
            #pragma unroll
            for (int g = 0; g < 4; g++) {
                const int row = g * H2n + lane;
                const float2* wp = (const float2*)(Whh2 + row * H2n);
                #pragma unroll
                for (int j = 0; j < 4; j++) { float2 f = wp[j]; w[4 * g + j] = pk2(f.x, f.y); }
            }
            h2ring[63 * RSTR + lane] = 0.0f;    // h2[-1] = 0 (read at t=2)
        }
        #pragma unroll
        for (int k = 0; k < 8; k++) w2h[k] = Wout[k];
        boutv = bout[0];
    } else { // wid 1,2 : K-split input-dot helpers (32/32)
        cell = lane >> 2;
        q    = lane & 3;
        const int row = q * H2n + cell;
        const int koff = (wid == 1) ? 0 : 32;
        const float2* wp = (const float2*)(Wih2 + row * H1n + koff);
        #pragma unroll
        for (int k = 0; k < 16; k++) { float2 f = wp[k]; w[k] = pk2(f.x, f.y); }
        bias2 = (wid == 1) ? b2[row] : 0.f;
    }
    if (tid < H1n) h1ring[3][tid] = 0.0f;       // h1[-1] = 0
    __syncthreads();

    float x_cur = xb[0];
    float x_n1  = xb[1];

    #pragma unroll 4
    for (int t = 0; t <= Tn + 1; ++t) {
        if (wid >= 3) {
            if (t < Tn) {
                float x_n2 = (t + 2 < Tn) ? xb[t + 2] : 0.0f;
                u64 a0 = pk2(fmaf(x_cur, wih, bias), 0.0f);
                u64 a1 = pk2(0.f, 0.f), a2 = a1, a3 = a1;
                const ulonglong2* hp = (const ulonglong2*)(&h1ring[(t + 3) & 3][0]);
                #pragma unroll
                for (int k = 0; k < 8; k++) {
                    ulonglong2 ha = hp[2 * k];
                    ulonglong2 hb = hp[2 * k + 1];
                    fma2(a0, w[4 * k + 0], ha.x);
                    fma2(a1, w[4 * k + 1], ha.y);
                    fma2(a2, w[4 * k + 2], hb.x);
                    fma2(a3, w[4 * k + 3], hb.y);
                }
                add2(a0, a1); add2(a2, a3); add2(a0, a2);
                float2 s2 = upk2(a0);
                float g = s2.x + s2.y;
                // single-MUFU activation: select the argument, not the result
                float arg = (q == 2) ? g : 0.5f * g;
                float th  = tanh_(arg);
                float act = (q == 2) ? th : fmaf(0.5f, th, 0.5f);
                const unsigned bl = lane & ~3u;
                float ai = __shfl_sync(0xffffffffu, act, bl + 0);
                float af = __shfl_sync(0xffffffffu, act, bl + 1);
                float ag = __shfl_sync(0xffffffffu, act, bl + 2);
                float ao = __shfl_sync(0xffffffffu, act, bl + 3);
                c1  = fmaf(af, c1, ai * ag);
                h1v = ao * tanh_(c1);
                if (q == 0) h1ring[t & 3][cell] = h1v;
                x_cur = x_n1;
                x_n1  = x_n2;
            }
        } else if (wid == 0) {
            if (t >= 2) {
                if (lane < H2n) {
                    const int s  = t - 2;
                    const int ph = (t - 1) & 1;
                    const float4 p0 = *(const float4*)&pbuf[ph][0][lane * 4];
                    const float4 p1 = *(const float4*)&pbuf[ph][1][lane * 4];
                    float gi = p0.x + p1.x;
                    float gf = p0.y + p1.y;
                    float gg = p0.z + p1.z;
                    float go = p0.w + p1.w;
                    // h2(t-1) from the ring (written by this warp at t-1)
                    const u64* hq = (const u64*)&h2ring[((t - 3) & (RING - 1)) * RSTR];
                    u64 h01 = hq[0], h23 = hq[1], h45 = hq[2], h67 = hq[3];
                    u64 A = pk2(gi, 0.f), B = pk2(gf, 0.f);
                    u64 C = pk2(gg, 0.f), D = pk2(go, 0.f);
                    fma2(A, w[0],  h01); fma2(B, w[4],  h01);
                    fma2(C, w[8],  h01); fma2(D, w[12], h01);
                    fma2(A, w[1],  h23); fma2(B, w[5],  h23);
                    fma2(C, w[9],  h23); fma2(D, w[13], h23);
                    fma2(A, w[2],  h45); fma2(B, w[6],  h45);
                    fma2(C, w[10], h45); fma2(D, w[14], h45);
                    fma2(A, w[3],  h67); fma2(B, w[7],  h67);
                    fma2(C, w[11], h67); fma2(D, w[15], h67);
                    float2 fa = upk2(A), fb = upk2(B), fc = upk2(C), fd = upk2(D);
                    float ti = sigm(fa.x + fa.y);
                    float tf = sigm(fb.x + fb.y);
                    float tg = tanh_(fc.x + fc.y);
                    float to = sigm(fd.x + fd.y);
                    c2  = fmaf(tf, c2, ti * tg);
                    h2v = to * tanh_(c2);
                    h2ring[(s & (RING - 1)) * RSTR + lane] = h2v;
                }
                // batched output projection (all 32 lanes, every 32 steps)
                if ((t & 31) == 0 && t >= 32) {
                    const int s2i = t - 34 + lane;
                    if (s2i >= 0) {
                        const float* r = &h2ring[(s2i & (RING - 1)) * RSTR];
                        float acc0 = boutv, acc1 = 0.f;
                        #pragma unroll
                        for (int k = 0; k < 4; k++) {
                            acc0 = fmaf(r[2 * k],     w2h[2 * k],     acc0);
                            acc1 = fmaf(r[2 * k + 1], w2h[2 * k + 1], acc1);
                        }
                        yb[s2i] = acc0 + acc1 + xb[s2i];
                    }
                }
            }
        } else { // wid 1,2 : layer-2 input-dot partials (for step s = t-1)
            if (t >= 1 && t <= Tn) {
                const int s = t - 1;
                u64 a0 = pk2(bias2, 0.0f), a1 = pk2(0.f, 0.f);
                const int koff = (wid == 1) ? 0 : 32;
                const ulonglong2* hp = (const ulonglong2*)(&h1ring[s & 3][koff]);
                #pragma unroll
                for (int k = 0; k < 4; k++) {
                    ulonglong2 ha = hp[2 * k];
                    ulonglong2 hb = hp[2 * k + 1];
                    fma2(a0, w[4 * k + 0], ha.x);
                    fma2(a1, w[4 * k + 1], ha.y);
                    fma2(a0, w[4 * k + 2], hb.x);
                    fma2(a1, w[4 * k + 3], hb.y);
                }
                add2(a0, a1);
                float2 s2 = upk2(a0);
                pbuf[t & 1][wid - 1][lane] = s2.x + s2.y;
            }
        }
        __syncthreads();
    }

    // tail: y for the last two steps (s = Tn-2, Tn-1) from the ring
    if (wid == 0 && lane < 2) {
        const int s2i = Tn - 2 + lane;
        const float* r = &h2ring[(s2i & (RING - 1)) * RSTR];
        float acc0 = boutv, acc1 = 0.f;
        #pragma unroll
        for (int k = 0; k < 4; k++) {
            acc0 = fmaf(r[2 * k],     w2h[2 * k],     acc0);
            acc1 = fmaf(r[2 * k + 1], w2h[2 * k + 1], acc1);
        }
        yb[s2i] = acc0 + acc1 + xb[s2i];
    }

    // final states: layout  y | h1 | c1 | h2 | c2  (each with leading dim 1)
    const int OH1 = Bsz * Tn;
    const int OC1 = OH1 + Bsz * H1n;
    const int OH2 = OC1 + Bsz * H1n;
    const int OC2 = OH2 + Bsz * H2n;
    if (wid >= 3) {
        if (q == 0) {
            out[OH1 + b * H1n + cell] = h1v;
            out[OC1 + b * H1n + cell] = c1;
        }
    } else if (wid == 0) {
        if (lane < H2n) {
            out[OH2 + b * H2n + lane] = h2v;
            out[OC2 + b * H2n + lane] = c2;
        }
    }
}

extern "C" void kernel_launch(void* const* d_in, const int* in_sizes, int n_in,
                              void* d_out, int out_size) {
    const float* x     = (const float*)d_in[0];
    const float* Wih1  = (const float*)d_in[1];
    const float* Whh1  = (const float*)d_in[2];
    const float* b1    = (const float*)d_in[3];
    const float* Wih2  = (const float*)d_in[4];
    const float* Whh2  = (const float*)d_in[5];
    const float* b2    = (const float*)d_in[6];
    const float* Wout  = (const float*)d_in[7];
    const float* bout  = (const float*)d_in[8];
    float* out = (float*)d_out;

    lstm2_kernel<<<Bsz, 352>>>(x, Wih1, Whh1, b1, Wih2, Whh2, b2, Wout, bout, out);
}